// round 7
// baseline (speedup 1.0000x reference)
#include <cuda_runtime.h>
#include <cuda_fp16.h>
#include <cstdint>

// ReprojectionLayer: out[b,j,x,y,z] = mean_c heatmaps[b,c,j, v*512+u]
//   (u,v) = reproLookup[c, sx+x, sy+y, sz+z, :], s* = clamp(trunc((center+160)/2)-52, 0, L-G)
//
// Strategy:
//   Pass 1: transpose+convert heatmaps [B,C,J,HW] fp32 -> T[B,C,HW,24] fp16
//           (48B rows = 2 sectors, three aligned 16B loads).
//   Pass 2: FOUR sequential gather launches, one per (batch, cam-half).
//           Each pass touches only 6 T-planes = 75.6 MB < L2 (126 MB), so the
//           ~4.3x row reuse hits L2 instead of DRAM. Output is accumulated
//           across the two half-passes (RMW), finalized with *1/12.
// Precision: values in [0,1); fp16 rel err <= 2^-11, fp32 accumulate.

#define NB 2
#define NC 12
#define NCP 6           // cams per gather pass
#define NJ 23
#define NJP 24
#define GG 104
#define HALFG 52
#define LL 160
#define HMW 512
#define HW (512 * 512)
#define G3 (GG * GG * GG)   // 1,124,864 (divisible by 256)

__device__ __forceinline__ uint32_t h2_to_u32(__half2 h) {
    return *reinterpret_cast<uint32_t*>(&h);
}
__device__ __forceinline__ __half2 u32_to_h2(uint32_t u) {
    return *reinterpret_cast<__half2*>(&u);
}

// Scratch: 2*12*262144 rows * 3 uint4 (48B) = 302 MB
__device__ uint4 g_T[(size_t)NB * NC * HW * 3];

// ---------------- Pass 1: transpose + fp32->fp16 ----------------
__global__ __launch_bounds__(256) void transpose_kernel(const float* __restrict__ hm)
{
    __shared__ float s[256 * 25];
    const int c = blockIdx.y, b = blockIdx.z;
    const int p0 = blockIdx.x * 256;
    const int tid = threadIdx.x;

    const float* src = hm + ((size_t)(b * NC + c) * NJ) * HW + p0 + tid;
#pragma unroll
    for (int j = 0; j < NJ; ++j)
        s[tid * 25 + j] = src[(size_t)j * HW];
    s[tid * 25 + 23] = 0.0f;
    __syncthreads();

    uint4* dst = g_T + ((size_t)(b * NC + c) * HW + p0) * 3;
#pragma unroll
    for (int i = tid; i < 256 * 3; i += 256) {
        const int pl = i / 3, part = i % 3;
        const float* sp = s + pl * 25 + part * 8;
        uint4 v;
        v.x = h2_to_u32(__floats2half2_rn(sp[0], sp[1]));
        v.y = h2_to_u32(__floats2half2_rn(sp[2], sp[3]));
        v.z = h2_to_u32(__floats2half2_rn(sp[4], sp[5]));
        v.w = h2_to_u32(__floats2half2_rn(sp[6], sp[7]));
        dst[i] = v;
    }
}

// ---------------- Pass 2: gather over 6 cams; FINAL pass does RMW + scale ----------------
template <int FINAL>
__global__ __launch_bounds__(256) void gather_pass(
    const float* __restrict__ center,
    const int2* __restrict__ lookup,
    float* __restrict__ out,
    int b, int cam0)
{
    const int vox = blockIdx.x * blockDim.x + threadIdx.x;  // grid exactly covers G3
    const int z = vox % GG;
    const int t = vox / GG;
    const int y = t % GG;
    const int x = t / GG;

    int sx = (int)((center[b * 3 + 0] + 160.0f) * 0.5f) - HALFG;
    int sy = (int)((center[b * 3 + 1] + 160.0f) * 0.5f) - HALFG;
    int sz = (int)((center[b * 3 + 2] + 160.0f) * 0.5f) - HALFG;
    sx = min(max(sx, 0), LL - GG);
    sy = min(max(sy, 0), LL - GG);
    sz = min(max(sz, 0), LL - GG);

    const int lx = sx + x, ly = sy + y, lz = sz + z;

    int base3[NCP];
#pragma unroll
    for (int c = 0; c < NCP; ++c) {
        const int cc = cam0 + c;
        const int lidx = ((cc * LL + lx) * LL + ly) * LL + lz;
        const int2 uv = __ldg(&lookup[lidx]);
        base3[c] = ((b * NC + cc) * HW + (uv.y * HMW + uv.x)) * 3;
    }

    float acc[NJP];
#pragma unroll
    for (int j = 0; j < NJP; ++j) acc[j] = 0.0f;

#pragma unroll
    for (int c = 0; c < NCP; ++c) {
        const uint4* row = g_T + base3[c];
#pragma unroll
        for (int part = 0; part < 3; ++part) {
            const uint4 q = __ldg(row + part);
            const float2 f0 = __half22float2(u32_to_h2(q.x));
            const float2 f1 = __half22float2(u32_to_h2(q.y));
            const float2 f2 = __half22float2(u32_to_h2(q.z));
            const float2 f3 = __half22float2(u32_to_h2(q.w));
            float* a = acc + part * 8;
            a[0] += f0.x; a[1] += f0.y;
            a[2] += f1.x; a[3] += f1.y;
            a[4] += f2.x; a[5] += f2.y;
            a[6] += f3.x; a[7] += f3.y;
        }
    }

    float* outb = out + ((size_t)b * NJ) * G3 + vox;
#pragma unroll
    for (int j = 0; j < NJ; ++j) {
        if (FINAL)
            outb[(size_t)j * G3] = (outb[(size_t)j * G3] + acc[j]) * (1.0f / 12.0f);
        else
            outb[(size_t)j * G3] = acc[j];
    }
}

extern "C" void kernel_launch(void* const* d_in, const int* in_sizes, int n_in,
                              void* d_out, int out_size)
{
    const float* heatmaps = (const float*)d_in[0];
    const float* center   = (const float*)d_in[1];
    const int2*  lookup   = (const int2*)d_in[2];
    float* out = (float*)d_out;

    {
        dim3 grid(HW / 256, NC, NB);
        transpose_kernel<<<grid, 256>>>(heatmaps);
    }
    const int nblk = G3 / 256;
    // Sequential passes keep the per-pass T working set (6 planes, 75.6 MB) L2-resident.
    gather_pass<0><<<nblk, 256>>>(center, lookup, out, 0, 0);
    gather_pass<1><<<nblk, 256>>>(center, lookup, out, 0, NCP);
    gather_pass<0><<<nblk, 256>>>(center, lookup, out, 1, 0);
    gather_pass<1><<<nblk, 256>>>(center, lookup, out, 1, NCP);
}

// round 8
// speedup vs baseline: 1.3873x; 1.3873x over previous
#include <cuda_runtime.h>
#include <cstdint>

// ReprojectionLayer: out[b,j,x,y,z] = mean_c heatmaps[b,c,j, v*512+u]
//   (u,v) = reproLookup[c, sx+x, sy+y, sz+z, :], s* = clamp(trunc((center+160)/2)-52, 0, L-G)
//
// Strategy (r8):
//   Pass 1: transpose+quantize heatmaps fp32 -> T[B,C,HW] rows of 23 u8 joints
//           padded to 32B => every gather row is EXACTLY ONE 32B sector,
//           fetched with 2 loads (uint4 + uint2, 24 meaningful bytes).
//   Pass 2: one gather launch per batch (12 cams each; 12 u8 planes = 101MB < L2,
//           so the ~4.3x row reuse hits L2). No output read-modify-write.
//           Integer SIMD accumulate in u16 lanes (sum <= 3060), final *1/(12*255).
// Precision: u8 quantization, RMS rel err after 12-cam mean ~6e-4 < 1e-3.

#define NB 2
#define NC 12
#define NJ 23
#define GG 104
#define HALFG 52
#define LL 160
#define HMW 512
#define HW (512 * 512)
#define G3 (GG * GG * GG)   // 1,124,864 (divisible by 256)

// Scratch: 2*12*262144 rows * 32B = 151 MB (2 uint4 per row)
__device__ uint4 g_T[(size_t)NB * NC * HW * 2];

// ---------------- Pass 1: transpose + fp32 -> u8 ----------------
// grid = (HW/256, NC, NB), block = 256. Each block: 256 pixels of one (b,c).
__global__ __launch_bounds__(256) void transpose_kernel(const float* __restrict__ hm)
{
    __shared__ float s[256 * 25];   // odd stride: conflict-free column reads
    const int c = blockIdx.y, b = blockIdx.z;
    const int p0 = blockIdx.x * 256;
    const int tid = threadIdx.x;

    const float* src = hm + ((size_t)(b * NC + c) * NJ) * HW + p0 + tid;
#pragma unroll
    for (int j = 0; j < NJ; ++j)
        s[tid * 25 + j] = src[(size_t)j * HW];      // coalesced across lanes
    s[tid * 25 + 23] = 0.0f;                        // (pad slot, unused)
    __syncthreads();

    // 256 rows * 2 uint4 (32B/row), fully contiguous writes
    uint4* dst = g_T + ((size_t)(b * NC + c) * HW + p0) * 2;
#pragma unroll
    for (int i = tid; i < 256 * 2; i += 256) {
        const int pl = i >> 1, part = i & 1;
        const float* sp = s + pl * 25;
        uint4 v;
        uint32_t w[4];
#pragma unroll
        for (int m = 0; m < 4; ++m) {
            uint32_t word = 0;
#pragma unroll
            for (int n = 0; n < 4; ++n) {
                const int jj = part * 16 + m * 4 + n;
                uint32_t q = 0;
                if (jj < NJ)
                    q = __float2uint_rn(sp[jj] * 255.0f);   // v in [0,1) -> q <= 255
                word |= q << (8 * n);
            }
            w[m] = word;
        }
        v.x = w[0]; v.y = w[1]; v.z = w[2]; v.w = w[3];
        dst[i] = v;
    }
}

// ---------------- Pass 2: gather 12 cams for one batch ----------------
__global__ __launch_bounds__(256) void gather_kernel(
    const float* __restrict__ center,
    const int2* __restrict__ lookup,
    float* __restrict__ out,
    int b)
{
    const int vox = blockIdx.x * blockDim.x + threadIdx.x;  // grid exactly covers G3
    const int z = vox % GG;
    const int t = vox / GG;
    const int y = t % GG;
    const int x = t / GG;

    int sx = (int)((center[b * 3 + 0] + 160.0f) * 0.5f) - HALFG;
    int sy = (int)((center[b * 3 + 1] + 160.0f) * 0.5f) - HALFG;
    int sz = (int)((center[b * 3 + 2] + 160.0f) * 0.5f) - HALFG;
    sx = min(max(sx, 0), LL - GG);
    sy = min(max(sy, 0), LL - GG);
    sz = min(max(sz, 0), LL - GG);

    const int lx = sx + x, ly = sy + y, lz = sz + z;

    int base2[NC];
#pragma unroll
    for (int c = 0; c < NC; ++c) {
        const int lidx = ((c * LL + lx) * LL + ly) * LL + lz;
        const int2 uv = __ldg(&lookup[lidx]);
        base2[c] = ((b * NC + c) * HW + (uv.y * HMW + uv.x)) * 2;
    }

    // u16-lane SIMD accumulators for joints 0..23 (words 0..5 of each row)
    uint32_t accLo[6] = {0, 0, 0, 0, 0, 0};   // bytes 0,2 of word w -> joints 4w, 4w+2
    uint32_t accHi[6] = {0, 0, 0, 0, 0, 0};   // bytes 1,3           -> joints 4w+1, 4w+3

#pragma unroll
    for (int c = 0; c < NC; ++c) {
        const uint4 q0 = __ldg(&g_T[base2[c]]);                              // bytes 0..15
        const uint2 q1 = __ldg(reinterpret_cast<const uint2*>(&g_T[base2[c] + 1])); // bytes 16..23
        const uint32_t w[6] = {q0.x, q0.y, q0.z, q0.w, q1.x, q1.y};
#pragma unroll
        for (int i = 0; i < 6; ++i) {
            accLo[i] += w[i] & 0x00FF00FFu;
            accHi[i] += (w[i] >> 8) & 0x00FF00FFu;
        }
    }

    const float scale = 1.0f / (12.0f * 255.0f);
    float* outb = out + ((size_t)b * NJ) * G3 + vox;
#pragma unroll
    for (int w = 0; w < 6; ++w) {
        const int j0 = 4 * w;
        outb[(size_t)(j0 + 0) * G3] = (float)(accLo[w] & 0xFFFFu) * scale;
        if (j0 + 1 < NJ) outb[(size_t)(j0 + 1) * G3] = (float)(accHi[w] & 0xFFFFu) * scale;
        if (j0 + 2 < NJ) outb[(size_t)(j0 + 2) * G3] = (float)(accLo[w] >> 16) * scale;
        if (j0 + 3 < NJ) outb[(size_t)(j0 + 3) * G3] = (float)(accHi[w] >> 16) * scale;
    }
}

extern "C" void kernel_launch(void* const* d_in, const int* in_sizes, int n_in,
                              void* d_out, int out_size)
{
    const float* heatmaps = (const float*)d_in[0];
    const float* center   = (const float*)d_in[1];
    const int2*  lookup   = (const int2*)d_in[2];
    float* out = (float*)d_out;

    {
        dim3 grid(HW / 256, NC, NB);
        transpose_kernel<<<grid, 256>>>(heatmaps);
    }
    const int nblk = G3 / 256;
    // Sequential per-batch passes: each keeps its 12 u8 planes (~101MB) L2-resident.
    gather_kernel<<<nblk, 256>>>(center, lookup, out, 0);
    gather_kernel<<<nblk, 256>>>(center, lookup, out, 1);
}

// round 9
// speedup vs baseline: 1.4692x; 1.0590x over previous
#include <cuda_runtime.h>
#include <cstdint>

// ReprojectionLayer: out[b,j,x,y,z] = mean_c heatmaps[b,c,j, v*512+u]
//   (u,v) = reproLookup[c, sx+x, sy+y, sz+z, :], s* = clamp(trunc((center+160)/2)-52, 0, L-G)
//
// Strategy (r9):
//   Pass 1: register-only transpose+quantize: each thread owns 4 consecutive
//           pixels, reads float4 per joint (coalesced), packs u8 joints into
//           6 words/row in registers, writes 4 rows = one full 128B line.
//           No smem, no barriers.
//   Pass 2: unchanged from r8 (best known): one gather launch per batch;
//           12 u8 planes = 101MB stay L2-resident; each (c,vox) row is one
//           32B sector fetched with uint4+uint2; u16-lane SIMD accumulate.
// Precision: u8 quantization -> rel_err ~6.4e-4 < 1e-3 (measured r8).

#define NB 2
#define NC 12
#define NJ 23
#define GG 104
#define HALFG 52
#define LL 160
#define HMW 512
#define HW (512 * 512)
#define G3 (GG * GG * GG)   // 1,124,864 (divisible by 256)

// Scratch: 2*12*262144 rows * 32B = 151 MB (2 uint4 per row)
__device__ uint4 g_T[(size_t)NB * NC * HW * 2];

// ---------------- Pass 1: transpose + fp32 -> u8 (register-only) ----------------
// grid = (HW/1024, NC, NB), block = 256. Thread t: pixels p0+4t .. p0+4t+3.
__global__ __launch_bounds__(256) void transpose_kernel(const float* __restrict__ hm)
{
    const int c = blockIdx.y, b = blockIdx.z;
    const int p0 = blockIdx.x * 1024;
    const int p = p0 + threadIdx.x * 4;

    const float4* src = reinterpret_cast<const float4*>(
        hm + ((size_t)(b * NC + c) * NJ) * HW + p);

    uint32_t w[4][6];
#pragma unroll
    for (int k = 0; k < 4; ++k)
#pragma unroll
        for (int i = 0; i < 6; ++i) w[k][i] = 0;

#pragma unroll
    for (int j = 0; j < NJ; ++j) {
        const float4 f = __ldg(src + (size_t)j * (HW / 4));
        const int word = j >> 2, sh = 8 * (j & 3);
        w[0][word] |= __float2uint_rn(f.x * 255.0f) << sh;
        w[1][word] |= __float2uint_rn(f.y * 255.0f) << sh;
        w[2][word] |= __float2uint_rn(f.z * 255.0f) << sh;
        w[3][word] |= __float2uint_rn(f.w * 255.0f) << sh;
    }

    // 4 rows * 32B = this thread's own 128B line; 8 contiguous STG.128
    uint4* dst = g_T + ((size_t)(b * NC + c) * HW + p) * 2;
#pragma unroll
    for (int k = 0; k < 4; ++k) {
        dst[2 * k]     = make_uint4(w[k][0], w[k][1], w[k][2], w[k][3]);
        dst[2 * k + 1] = make_uint4(w[k][4], w[k][5], 0u, 0u);
    }
}

// ---------------- Pass 2: gather 12 cams for one batch (unchanged r8) ----------------
__global__ __launch_bounds__(256) void gather_kernel(
    const float* __restrict__ center,
    const int2* __restrict__ lookup,
    float* __restrict__ out,
    int b)
{
    const int vox = blockIdx.x * blockDim.x + threadIdx.x;  // grid exactly covers G3
    const int z = vox % GG;
    const int t = vox / GG;
    const int y = t % GG;
    const int x = t / GG;

    int sx = (int)((center[b * 3 + 0] + 160.0f) * 0.5f) - HALFG;
    int sy = (int)((center[b * 3 + 1] + 160.0f) * 0.5f) - HALFG;
    int sz = (int)((center[b * 3 + 2] + 160.0f) * 0.5f) - HALFG;
    sx = min(max(sx, 0), LL - GG);
    sy = min(max(sy, 0), LL - GG);
    sz = min(max(sz, 0), LL - GG);

    const int lx = sx + x, ly = sy + y, lz = sz + z;

    int base2[NC];
#pragma unroll
    for (int c = 0; c < NC; ++c) {
        const int lidx = ((c * LL + lx) * LL + ly) * LL + lz;
        const int2 uv = __ldg(&lookup[lidx]);
        base2[c] = ((b * NC + c) * HW + (uv.y * HMW + uv.x)) * 2;
    }

    uint32_t accLo[6] = {0, 0, 0, 0, 0, 0};   // joints 4w, 4w+2 in u16 lanes
    uint32_t accHi[6] = {0, 0, 0, 0, 0, 0};   // joints 4w+1, 4w+3

#pragma unroll
    for (int c = 0; c < NC; ++c) {
        const uint4 q0 = __ldg(&g_T[base2[c]]);
        const uint2 q1 = __ldg(reinterpret_cast<const uint2*>(&g_T[base2[c] + 1]));
        const uint32_t w[6] = {q0.x, q0.y, q0.z, q0.w, q1.x, q1.y};
#pragma unroll
        for (int i = 0; i < 6; ++i) {
            accLo[i] += w[i] & 0x00FF00FFu;
            accHi[i] += (w[i] >> 8) & 0x00FF00FFu;
        }
    }

    const float scale = 1.0f / (12.0f * 255.0f);
    float* outb = out + ((size_t)b * NJ) * G3 + vox;
#pragma unroll
    for (int w = 0; w < 6; ++w) {
        const int j0 = 4 * w;
        outb[(size_t)(j0 + 0) * G3] = (float)(accLo[w] & 0xFFFFu) * scale;
        if (j0 + 1 < NJ) outb[(size_t)(j0 + 1) * G3] = (float)(accHi[w] & 0xFFFFu) * scale;
        if (j0 + 2 < NJ) outb[(size_t)(j0 + 2) * G3] = (float)(accLo[w] >> 16) * scale;
        if (j0 + 3 < NJ) outb[(size_t)(j0 + 3) * G3] = (float)(accHi[w] >> 16) * scale;
    }
}

extern "C" void kernel_launch(void* const* d_in, const int* in_sizes, int n_in,
                              void* d_out, int out_size)
{
    const float* heatmaps = (const float*)d_in[0];
    const float* center   = (const float*)d_in[1];
    const int2*  lookup   = (const int2*)d_in[2];
    float* out = (float*)d_out;

    {
        dim3 grid(HW / 1024, NC, NB);
        transpose_kernel<<<grid, 256>>>(heatmaps);
    }
    const int nblk = G3 / 256;
    // Sequential per-batch passes: each keeps its 12 u8 planes (~101MB) L2-resident.
    gather_kernel<<<nblk, 256>>>(center, lookup, out, 0);
    gather_kernel<<<nblk, 256>>>(center, lookup, out, 1);
}

// round 10
// speedup vs baseline: 1.4864x; 1.0117x over previous
#include <cuda_runtime.h>
#include <cstdint>

// ReprojectionLayer: out[b,j,x,y,z] = mean_c heatmaps[b,c,j, v*512+u]
//   (u,v) = reproLookup[c, sx+x, sy+y, sz+z, :], s* = clamp(trunc((center+160)/2)-52, 0, L-G)
//
// Strategy (r10):
//   Pass 1 (r9, unchanged): register-only transpose+quantize fp32 -> u8 rows
//           T[B,C,HW] of 23 joints padded to 32B (one sector per row).
//   Pass 2: one launch per batch (12 u8 planes = 101MB, L2-resident).
//           NEW: pair-lane row fetch — two lanes load the two 16B halves of one
//           row, so each warp-gather LDG touches ~16 distinct 128B lines instead
//           of 32, hitting the 32-sector/warp-cam wavefront floor (2x fewer
//           L1tex wavefronts). Reassemble per-voxel sums with warp shuffles.
// Precision: u8 quantization -> rel_err ~6.4e-4 < 1e-3 (measured r8/r9).

#define NB 2
#define NC 12
#define NJ 23
#define GG 104
#define HALFG 52
#define LL 160
#define HMW 512
#define HW (512 * 512)
#define G3 (GG * GG * GG)   // 1,124,864 = 4394 * 256, warps always full

// Scratch: 2*12*262144 rows * 32B = 151 MB (2 uint4 per row)
__device__ uint4 g_T[(size_t)NB * NC * HW * 2];

// ---------------- Pass 1: transpose + fp32 -> u8 (register-only, r9) ----------------
__global__ __launch_bounds__(256) void transpose_kernel(const float* __restrict__ hm)
{
    const int c = blockIdx.y, b = blockIdx.z;
    const int p = blockIdx.x * 1024 + threadIdx.x * 4;

    const float4* src = reinterpret_cast<const float4*>(
        hm + ((size_t)(b * NC + c) * NJ) * HW + p);

    uint32_t w[4][6];
#pragma unroll
    for (int k = 0; k < 4; ++k)
#pragma unroll
        for (int i = 0; i < 6; ++i) w[k][i] = 0;

#pragma unroll
    for (int j = 0; j < NJ; ++j) {
        const float4 f = __ldg(src + (size_t)j * (HW / 4));
        const int word = j >> 2, sh = 8 * (j & 3);
        w[0][word] |= __float2uint_rn(f.x * 255.0f) << sh;
        w[1][word] |= __float2uint_rn(f.y * 255.0f) << sh;
        w[2][word] |= __float2uint_rn(f.z * 255.0f) << sh;
        w[3][word] |= __float2uint_rn(f.w * 255.0f) << sh;
    }

    uint4* dst = g_T + ((size_t)(b * NC + c) * HW + p) * 2;
#pragma unroll
    for (int k = 0; k < 4; ++k) {
        dst[2 * k]     = make_uint4(w[k][0], w[k][1], w[k][2], w[k][3]);
        dst[2 * k + 1] = make_uint4(w[k][4], w[k][5], 0u, 0u);
    }
}

// ---------------- Pass 2: gather, pair-lane row fetch ----------------
__global__ __launch_bounds__(256) void gather_kernel(
    const float* __restrict__ center,
    const int2* __restrict__ lookup,
    float* __restrict__ out,
    int b)
{
    const int lane = threadIdx.x & 31;
    const int vox = blockIdx.x * blockDim.x + threadIdx.x;   // grid covers G3 exactly

    const int z = vox % GG;
    const int t = vox / GG;
    const int y = t % GG;
    const int x = t / GG;

    int sx = (int)((center[b * 3 + 0] + 160.0f) * 0.5f) - HALFG;
    int sy = (int)((center[b * 3 + 1] + 160.0f) * 0.5f) - HALFG;
    int sz = (int)((center[b * 3 + 2] + 160.0f) * 0.5f) - HALFG;
    sx = min(max(sx, 0), LL - GG);
    sy = min(max(sy, 0), LL - GG);
    sz = min(max(sz, 0), LL - GG);

    const int lx = sx + x, ly = sy + y, lz = sz + z;

    int base2[NC];
#pragma unroll
    for (int c = 0; c < NC; ++c) {
        const int lidx = ((c * LL + lx) * LL + ly) * LL + lz;
        const int2 uv = __ldg(&lookup[lidx]);
        base2[c] = ((b * NC + c) * HW + (uv.y * HMW + uv.x)) * 2;
    }

    // Per-lane partial accumulators. h indexes which 16-voxel half of the warp
    // the loaded row belongs to. Even lanes carry words 0-3 (joints 0-15) of
    // row (16h + lane/2); odd lanes carry words 4-5 (joints 16-23; 6-7 pad=0).
    uint32_t accLo[2][4] = {{0,0,0,0},{0,0,0,0}};
    uint32_t accHi[2][4] = {{0,0,0,0},{0,0,0,0}};
    const int srcRow = lane >> 1;       // which row of the half this lane serves
    const int part = lane & 1;          // 16B half of the 32B row

#pragma unroll
    for (int c = 0; c < NC; ++c) {
#pragma unroll
        for (int h = 0; h < 2; ++h) {
            const int rowbase = __shfl_sync(0xffffffffu, base2[c], (h << 4) + srcRow);
            const uint4 q = __ldg(&g_T[rowbase + part]);   // pair lanes share one sector
            accLo[h][0] += q.x & 0x00FF00FFu;  accHi[h][0] += (q.x >> 8) & 0x00FF00FFu;
            accLo[h][1] += q.y & 0x00FF00FFu;  accHi[h][1] += (q.y >> 8) & 0x00FF00FFu;
            accLo[h][2] += q.z & 0x00FF00FFu;  accHi[h][2] += (q.z >> 8) & 0x00FF00FFu;
            accLo[h][3] += q.w & 0x00FF00FFu;  accHi[h][3] += (q.w >> 8) & 0x00FF00FFu;
        }
    }

    // Reassemble my voxel's sums: my row lives at (h = lane/16, k = lane%15+1... lane&15):
    //   even source lane 2k  -> joints 0-15  (its acc words 0-3)
    //   odd  source lane 2k+1-> joints 16-23 (its acc words 0-1)
    const int k = lane & 15;
    const bool hi = lane >= 16;
    uint32_t eLo[4], eHi[4], oLo[2], oHi[2];
#pragma unroll
    for (int w = 0; w < 4; ++w) {
        const uint32_t a0 = __shfl_sync(0xffffffffu, accLo[0][w], 2 * k);
        const uint32_t a1 = __shfl_sync(0xffffffffu, accLo[1][w], 2 * k);
        eLo[w] = hi ? a1 : a0;
        const uint32_t b0 = __shfl_sync(0xffffffffu, accHi[0][w], 2 * k);
        const uint32_t b1 = __shfl_sync(0xffffffffu, accHi[1][w], 2 * k);
        eHi[w] = hi ? b1 : b0;
    }
#pragma unroll
    for (int w = 0; w < 2; ++w) {
        const uint32_t a0 = __shfl_sync(0xffffffffu, accLo[0][w], 2 * k + 1);
        const uint32_t a1 = __shfl_sync(0xffffffffu, accLo[1][w], 2 * k + 1);
        oLo[w] = hi ? a1 : a0;
        const uint32_t b0 = __shfl_sync(0xffffffffu, accHi[0][w], 2 * k + 1);
        const uint32_t b1 = __shfl_sync(0xffffffffu, accHi[1][w], 2 * k + 1);
        oHi[w] = hi ? b1 : b0;
    }

    const float scale = 1.0f / (12.0f * 255.0f);
    float* outb = out + ((size_t)b * NJ) * G3 + vox;
#pragma unroll
    for (int w = 0; w < 4; ++w) {          // joints 0..15
        const int j0 = 4 * w;
        outb[(size_t)(j0 + 0) * G3] = (float)(eLo[w] & 0xFFFFu) * scale;
        outb[(size_t)(j0 + 1) * G3] = (float)(eHi[w] & 0xFFFFu) * scale;
        outb[(size_t)(j0 + 2) * G3] = (float)(eLo[w] >> 16) * scale;
        outb[(size_t)(j0 + 3) * G3] = (float)(eHi[w] >> 16) * scale;
    }
#pragma unroll
    for (int w = 0; w < 2; ++w) {          // joints 16..23 (skip pad j23)
        const int j0 = 16 + 4 * w;
        outb[(size_t)(j0 + 0) * G3] = (float)(oLo[w] & 0xFFFFu) * scale;
        outb[(size_t)(j0 + 1) * G3] = (float)(oHi[w] & 0xFFFFu) * scale;
        outb[(size_t)(j0 + 2) * G3] = (float)(oLo[w] >> 16) * scale;
        if (j0 + 3 < NJ)
            outb[(size_t)(j0 + 3) * G3] = (float)(oHi[w] >> 16) * scale;
    }
}

extern "C" void kernel_launch(void* const* d_in, const int* in_sizes, int n_in,
                              void* d_out, int out_size)
{
    const float* heatmaps = (const float*)d_in[0];
    const float* center   = (const float*)d_in[1];
    const int2*  lookup   = (const int2*)d_in[2];
    float* out = (float*)d_out;

    {
        dim3 grid(HW / 1024, NC, NB);
        transpose_kernel<<<grid, 256>>>(heatmaps);
    }
    const int nblk = G3 / 256;
    // Sequential per-batch passes: each keeps its 12 u8 planes (~101MB) L2-resident.
    gather_kernel<<<nblk, 256>>>(center, lookup, out, 0);
    gather_kernel<<<nblk, 256>>>(center, lookup, out, 1);
}